// round 12
// baseline (speedup 1.0000x reference)
#include <cuda_runtime.h>
#include <cuda_fp16.h>
#include <cstdint>

#define NIMG 8
#define HW 16384           // 128*128
#define IMGSZ (64*HW)

// Scratch (device globals)
__device__ __half g_ufh[NIMG*IMGSZ];   // fp16 activations, plane layout [img][ci][px]
__device__ __half g_vfh[NIMG*IMGSZ];
__device__ float  g_ov[NIMG*IMGSZ];    // v-branch conv output (u-branch is fused)
// fp16 conv weights, k16 B-frag layout:
// [br(2)][cgp(4)][tap(9)][co(64)][rid(4)][pp(2)] of half2
__device__ uint32_t g_wPh[2*4*9*64*4*2];

// fp16 k16 mma: A 4 regs, B 2 regs, C 4 f32
__device__ __forceinline__ void mma_f16(float* c, const uint32_t* a, const uint32_t* b){
  asm volatile(
    "mma.sync.aligned.m16n8k16.row.col.f32.f16.f16.f32 "
    "{%0,%1,%2,%3}, {%4,%5,%6,%7}, {%8,%9}, {%0,%1,%2,%3};"
    : "+f"(c[0]), "+f"(c[1]), "+f"(c[2]), "+f"(c[3])
    : "r"(a[0]), "r"(a[1]), "r"(a[2]), "r"(a[3]), "r"(b[0]), "r"(b[1]));
}

// ---------------------------------------------------------------------------
// K0: pack fp16 conv weights into k16 B-frag layout.
// ---------------------------------------------------------------------------
__global__ void k_prep_w(const float* __restrict__ conv_w){
  int idx = blockIdx.x*256 + threadIdx.x;    // 36864 total
  if (idx >= 36864) return;
  int pp  = idx & 1;
  int rid = (idx >> 1) & 3;
  int co  = (idx >> 3) & 63;
  int tap = (idx >> 9) % 9;
  int rest= (idx >> 9) / 9;
  int cgp = rest & 3;
  int br  = rest >> 2;
  int ci  = cgp*16 + 2*rid + 8*pp;
  float w0 = conv_w[(co*128 + br*64 + ci)*9 + tap];
  float w1 = conv_w[(co*128 + br*64 + ci + 1)*9 + tap];
  __half2 h = __floats2half2_rn(w0, w1);
  g_wPh[idx] = *(uint32_t*)&h;
}

// ---------------------------------------------------------------------------
// K1: fused (both branches) 1x1 conv + BN + ReLU via FP16 mma.
// grid (512, 2): blockIdx.y selects branch.
// ---------------------------------------------------------------------------
#define PW_PA 36
#define PW_PX 264
#define PW_AW (64*PW_PA)
#define PW_XW (32*PW_PX)
#define PW_SMEM ((PW_AW + PW_XW + 128)*4)

__global__ void __launch_bounds__(256, 2) k_pw_mma(
    const float* __restrict__ xu, const float* __restrict__ xv,
    const float* __restrict__ wu, const float* __restrict__ wv,
    const float* __restrict__ gammau, const float* __restrict__ gammav,
    const float* __restrict__ betau,  const float* __restrict__ betav,
    const float* __restrict__ meanu,  const float* __restrict__ meanv,
    const float* __restrict__ varu,   const float* __restrict__ varv)
{
  extern __shared__ uint32_t S[];
  uint32_t* sA = S;
  uint32_t* sX = S + PW_AW;
  float* sScale = (float*)(S + PW_AW + PW_XW);
  float* sShift = sScale + 64;

  int sel = blockIdx.y;
  const float* x     = sel ? xv : xu;
  const float* w     = sel ? wv : wu;
  const float* gamma = sel ? gammav : gammau;
  const float* beta  = sel ? betav  : betau;
  const float* mean  = sel ? meanv  : meanu;
  const float* var   = sel ? varv   : varu;
  __half* out = sel ? g_vfh : g_ufh;

  int tid  = threadIdx.x;
  int wid  = tid >> 5;
  int lane = tid & 31;
  int qid  = lane >> 2;
  int rid  = lane & 3;

  int img = blockIdx.x >> 6;
  int px0 = (blockIdx.x & 63) << 8;
  const float* xi = x + (size_t)img*IMGSZ + px0;

  for (int i = tid; i < 2048; i += 256){
    int co = i >> 5, pr = i & 31;
    float2 v = *(const float2*)(w + co*64 + pr*2);
    __half2 h = __floats2half2_rn(v.x, v.y);
    sA[co*PW_PA + pr] = *(uint32_t*)&h;
  }
  if (tid < 64){
    float la = gamma[tid]*rsqrtf(var[tid]+1e-5f);
    sScale[tid] = la;
    sShift[tid] = beta[tid] - mean[tid]*la;
  }
  #pragma unroll
  for (int pl = 0; pl < 4; ++pl){
    int p = wid*4 + pl;
    const float* pe = xi + (size_t)(2*p)*HW;
    const float* po = xi + (size_t)(2*p+1)*HW;
    uint32_t* d = sX + p*PW_PX;
    #pragma unroll
    for (int rep = 0; rep < 8; ++rep){
      int px = lane + rep*32;
      __half2 h = __floats2half2_rn(pe[px], po[px]);
      d[px] = *(uint32_t*)&h;
    }
  }
  __syncthreads();

  int pw0 = wid << 5;
  float acc[4][4][4];
  #pragma unroll
  for (int t=0;t<4;t++)
    #pragma unroll
    for (int n=0;n<4;n++)
      #pragma unroll
      for (int e=0;e<4;e++) acc[t][n][e]=0.f;

  #pragma unroll
  for (int ks = 0; ks < 4; ++ks){
    int c0p = ks*8;
    uint32_t bfr[4][2];
    #pragma unroll
    for (int n8 = 0; n8 < 4; ++n8){
      bfr[n8][0] = sX[(c0p+rid)*PW_PX   + pw0 + n8*8 + qid];
      bfr[n8][1] = sX[(c0p+4+rid)*PW_PX + pw0 + n8*8 + qid];
    }
    #pragma unroll
    for (int t = 0; t < 4; ++t){
      const uint32_t* ap = sA + (t*16 + qid)*PW_PA + c0p + rid;
      uint32_t afr[4];
      afr[0] = ap[0];
      afr[1] = ap[8*PW_PA];
      afr[2] = ap[4];
      afr[3] = ap[8*PW_PA + 4];
      #pragma unroll
      for (int n8 = 0; n8 < 4; ++n8)
        mma_f16(acc[t][n8], afr, bfr[n8]);
    }
  }

  __half* ob = out + (size_t)img*IMGSZ + px0 + pw0;
  #pragma unroll
  for (int t = 0; t < 4; ++t){
    int co0t = t*16 + qid;
    float la0 = sScale[co0t],   sa0 = sShift[co0t];
    float la1 = sScale[co0t+8], sa1 = sShift[co0t+8];
    #pragma unroll
    for (int n8 = 0; n8 < 4; ++n8){
      int pc = n8*8 + rid*2;
      __half2 h0 = __floats2half2_rn(
          fmaxf(fmaf(acc[t][n8][0], la0, sa0), 0.f),
          fmaxf(fmaf(acc[t][n8][1], la0, sa0), 0.f));
      __half2 h1 = __floats2half2_rn(
          fmaxf(fmaf(acc[t][n8][2], la1, sa1), 0.f),
          fmaxf(fmaf(acc[t][n8][3], la1, sa1), 0.f));
      *(uint32_t*)(ob + (size_t)co0t*HW + pc)     = *(uint32_t*)&h0;
      *(uint32_t*)(ob + (size_t)(co0t+8)*HW + pc) = *(uint32_t*)&h1;
    }
  }
}

// ---------------------------------------------------------------------------
// K2: 3x3 conv, mma.sync FP16 m16n8k16, v7: fused broadcast epilogue.
// phase 0: v-branch -> writes g_ov (transpose epilogue, coalesced STG.128)
// phase 1: u-branch -> epilogue computes (acc + bias) + ov[b,sy] for sy=0..3
//                      and writes the FINAL output directly (bcast eliminated).
// Per-warp smem slab transpose (reuses A-tile smem after syncthreads):
// slab[co_l(32)][pitch 20] floats -> STS conflict-free (banks 8*rid+qid).
// ---------------------------------------------------------------------------
#define GSTR 212                 // uint2 per group slice (6*35 + 2 pad)
#define AROWP 35                 // uint2 per row
#define SLABP 20                 // slab pitch (floats)
#define CONV_SMEM (16*GSTR*8)    // 27136 B (mainloop); slab 8*640*4=20.5KB fits

__global__ void __launch_bounds__(256, 4) k_conv_mma(
    int phase, const float* __restrict__ bias, float* __restrict__ finout)
{
  extern __shared__ uint2 sA2[];   // [group(16)][6r][35c]

  int tid  = threadIdx.x;
  int wid  = tid >> 5;
  int lane = tid & 31;
  int qid  = lane >> 2;
  int rid  = lane & 3;

  int bx  = blockIdx.x;
  int img = bx >> 7;               // 0..7
  int t   = bx & 127;
  int h0  = (t >> 2) << 2;
  int w0  = (t & 3)  << 5;
  // phase 0 = v branch (weights br=1, acts g_vfh); phase 1 = u branch (br=0)
  const __half* in = (phase ? g_ufh : g_vfh) + (size_t)img*IMGSZ;
  const uint32_t* wsrc = g_wPh + (size_t)(phase ? 0 : 18432);

  // Stage A tile: warp wid handles groups g = wid*2, wid*2+1.
  #pragma unroll
  for (int sub = 0; sub < 2; ++sub){
    int g  = wid*2 + sub;
    int P1 = ((g >> 2)*8) + (g & 3);
    const __half* p0 = in + (size_t)(2*P1)*HW;
    const __half* p1 = in + (size_t)(2*P1+1)*HW;
    const __half* p2 = in + (size_t)(2*P1+8)*HW;
    const __half* p3 = in + (size_t)(2*P1+9)*HW;
    uint2* dst = sA2 + g*GSTR;
    #pragma unroll
    for (int r = 0; r < 6; ++r){
      int gh = h0 + r - 1;
      bool vr = (unsigned)gh < 128u;
      int gw = w0 - 1 + lane;
      bool ok = vr && ((unsigned)gw < 128u);
      int off = gh*128 + gw;
      __half a = ok ? p0[off] : __half(0.f);
      __half b = ok ? p1[off] : __half(0.f);
      __half c = ok ? p2[off] : __half(0.f);
      __half d = ok ? p3[off] : __half(0.f);
      __half2 hx = __halves2half2(a, b);
      __half2 hy = __halves2half2(c, d);
      uint2 val; val.x = *(uint32_t*)&hx; val.y = *(uint32_t*)&hy;
      dst[r*AROWP + lane] = val;
      if (lane < 2){
        int gw2 = gw + 32;
        bool ok2 = vr && ((unsigned)gw2 < 128u);
        int off2 = gh*128 + gw2;
        __half a2 = ok2 ? p0[off2] : __half(0.f);
        __half b2 = ok2 ? p1[off2] : __half(0.f);
        __half c2 = ok2 ? p2[off2] : __half(0.f);
        __half d2 = ok2 ? p3[off2] : __half(0.f);
        __half2 hx2 = __halves2half2(a2, b2);
        __half2 hy2 = __halves2half2(c2, d2);
        uint2 v2; v2.x = *(uint32_t*)&hx2; v2.y = *(uint32_t*)&hy2;
        dst[r*AROWP + lane + 32] = v2;
      }
    }
  }
  __syncthreads();

  int warpM = wid & 3;
  int co0   = (wid >> 2) << 5;

  float acc[2][4][4];
  #pragma unroll
  for (int a=0;a<2;a++)
    #pragma unroll
    for (int b=0;b<4;b++)
      #pragma unroll
      for (int e=0;e<4;e++) acc[a][b][e]=0.f;

  const uint2* Bb0 = (const uint2*)wsrc + (co0 + qid)*4 + rid;

  #pragma unroll
  for (int cgp = 0; cgp < 4; ++cgp){
    const uint2* Ab = sA2 + (cgp*4 + rid)*GSTR + warpM*AROWP + qid;
    const uint2* Bb = Bb0 + cgp*2304;

    #pragma unroll
    for (int tap = 0; tap < 9; ++tap){
      int ky = tap / 3;
      int kx = tap - ky*3;
      int aoff = ky*AROWP + kx;

      uint32_t bfr[4][2];
      #pragma unroll
      for (int n8 = 0; n8 < 4; ++n8){
        uint2 bp = __ldg(Bb + tap*256 + n8*32);
        bfr[n8][0] = bp.x;
        bfr[n8][1] = bp.y;
      }
      #pragma unroll
      for (int tt = 0; tt < 2; ++tt){
        uint2 v1 = Ab[aoff + tt*16];
        uint2 v2 = Ab[aoff + tt*16 + 8];
        uint32_t afr[4];
        afr[0] = v1.x;
        afr[1] = v2.x;
        afr[2] = v1.y;
        afr[3] = v2.y;
        #pragma unroll
        for (int n8 = 0; n8 < 4; ++n8)
          mma_f16(acc[tt][n8], afr, bfr[n8]);
      }
    }
  }

  // ---- transpose epilogue (reuse sA2 as per-warp slabs) ----
  __syncthreads();     // all warps done reading A tile
  float* slab = (float*)sA2 + wid*(32*SLABP);   // 640 floats per warp
  int h = h0 + warpM;
  int b  = img >> 2;
  int sx = img & 3;

  #pragma unroll
  for (int tt = 0; tt < 2; ++tt){
    // scatter acc into slab[co_l][px_l] (banks 8*rid+qid: conflict-free)
    #pragma unroll
    for (int n8 = 0; n8 < 4; ++n8){
      int ca = n8*8 + rid*2;
      slab[ca*SLABP + qid]          = acc[tt][n8][0];
      slab[(ca+1)*SLABP + qid]      = acc[tt][n8][1];
      slab[ca*SLABP + qid + 8]      = acc[tt][n8][2];
      slab[(ca+1)*SLABP + qid + 8]  = acc[tt][n8][3];
    }
    __syncwarp();
    // gather float4 over px and store coalesced
    int quad = lane & 3;
    int pxw  = w0 + tt*16 + quad*4;
    size_t rowoff = (size_t)h*128 + pxw;
    #pragma unroll
    for (int k = 0; k < 4; ++k){
      int co_l = (lane >> 2) + k*8;
      int co   = co0 + co_l;
      float4 a = *(float4*)(slab + co_l*SLABP + quad*4);
      if (phase == 0){
        // v branch: plain store to g_ov
        *(float4*)(g_ov + (size_t)img*IMGSZ + (size_t)co*HW + rowoff) = a;
      } else {
        // u branch: fused broadcast add -> final output
        float bi = __ldg(bias + co);
        a.x += bi; a.y += bi; a.z += bi; a.w += bi;
        size_t poff = (size_t)co*HW + rowoff;
        #pragma unroll
        for (int sy = 0; sy < 4; ++sy){
          float4 vv = __ldg((const float4*)(g_ov + (size_t)(b*4+sy)*IMGSZ + poff));
          float4 o;
          o.x = a.x + vv.x;
          o.y = a.y + vv.y;
          o.z = a.z + vv.z;
          o.w = a.w + vv.w;
          size_t opl = (size_t)(((b*4+sx)*4 + sy)*64 + co);
          __stcs((float4*)(finout + opl*HW + rowoff), o);
        }
      }
    }
    __syncwarp();     // before next tt reuses slab
  }
}

// ---------------------------------------------------------------------------
extern "C" void kernel_launch(void* const* d_in, const int* in_sizes, int n_in,
                              void* d_out, int out_size)
{
  const float* u        = (const float*)d_in[0];
  const float* v        = (const float*)d_in[1];
  const float* pu_w     = (const float*)d_in[2];
  const float* pu_gamma = (const float*)d_in[3];
  const float* pu_beta  = (const float*)d_in[4];
  const float* pu_mean  = (const float*)d_in[5];
  const float* pu_var   = (const float*)d_in[6];
  const float* pv_w     = (const float*)d_in[7];
  const float* pv_gamma = (const float*)d_in[8];
  const float* pv_beta  = (const float*)d_in[9];
  const float* pv_mean  = (const float*)d_in[10];
  const float* pv_var   = (const float*)d_in[11];
  const float* conv_w   = (const float*)d_in[12];
  const float* conv_b   = (const float*)d_in[13];
  float* out = (float*)d_out;

  static int attr_set = 0;
  if (!attr_set){
    cudaFuncSetAttribute(k_pw_mma,   cudaFuncAttributeMaxDynamicSharedMemorySize, PW_SMEM);
    cudaFuncSetAttribute(k_conv_mma, cudaFuncAttributeMaxDynamicSharedMemorySize, CONV_SMEM);
    attr_set = 1;
  }

  k_prep_w<<<144, 256>>>(conv_w);

  dim3 pwg(512, 2);
  k_pw_mma<<<pwg, 256, PW_SMEM>>>(u, v, pu_w, pv_w, pu_gamma, pv_gamma,
                                  pu_beta, pv_beta, pu_mean, pv_mean,
                                  pu_var, pv_var);

  // v branch first (writes g_ov), then u branch with fused broadcast add
  k_conv_mma<<<1024, 256, CONV_SMEM>>>(0, conv_b, out);
  k_conv_mma<<<1024, 256, CONV_SMEM>>>(1, conv_b, out);
}

// round 13
// speedup vs baseline: 1.2280x; 1.2280x over previous
#include <cuda_runtime.h>
#include <cuda_fp16.h>
#include <cstdint>

#define NIMG 8
#define HW 16384           // 128*128
#define IMGSZ (64*HW)

// Scratch (device globals)
__device__ __half g_ufh[NIMG*IMGSZ];   // fp16 activations, plane layout [img][ci][px]
__device__ __half g_vfh[NIMG*IMGSZ];
__device__ float  g_ou[NIMG*IMGSZ];
__device__ float  g_ov[NIMG*IMGSZ];
// fp16 conv weights, k16 B-frag layout v2 (per-thread n8 quads contiguous):
// uint2 index = ((((br*4+cgp)*9+tap)*2+warpN)*32+lane)*4 + n8 ; .x=pp0,.y=pp1
__device__ uint32_t g_wB2[2*4*9*2*32*4*2];

// fp16 k16 mma: A 4 regs, B 2 regs, C 4 f32
__device__ __forceinline__ void mma_f16(float* c, const uint32_t* a, const uint32_t* b){
  asm volatile(
    "mma.sync.aligned.m16n8k16.row.col.f32.f16.f16.f32 "
    "{%0,%1,%2,%3}, {%4,%5,%6,%7}, {%8,%9}, {%0,%1,%2,%3};"
    : "+f"(c[0]), "+f"(c[1]), "+f"(c[2]), "+f"(c[3])
    : "r"(a[0]), "r"(a[1]), "r"(a[2]), "r"(a[3]), "r"(b[0]), "r"(b[1]));
}

// ---------------------------------------------------------------------------
// K1: fused 1x1 conv + BN + ReLU via FP16 mma, grid (512, 3).
// blockIdx.y: 0 = u branch, 1 = v branch, 2 = weight repack for the 3x3 conv.
// ---------------------------------------------------------------------------
#define PW_PA 36
#define PW_PX 264
#define PW_AW (64*PW_PA)
#define PW_XW (32*PW_PX)
#define PW_SMEM ((PW_AW + PW_XW + 128)*4)

__global__ void __launch_bounds__(256, 2) k_pw_mma(
    const float* __restrict__ xu, const float* __restrict__ xv,
    const float* __restrict__ wu, const float* __restrict__ wv,
    const float* __restrict__ gammau, const float* __restrict__ gammav,
    const float* __restrict__ betau,  const float* __restrict__ betav,
    const float* __restrict__ meanu,  const float* __restrict__ meanv,
    const float* __restrict__ varu,   const float* __restrict__ varv,
    const float* __restrict__ conv_w)
{
  int tid  = threadIdx.x;

  // ---- branch 2: repack 3x3 conv weights into B-frag quad layout ----
  if (blockIdx.y == 2){
    int idx = blockIdx.x*256 + tid;
    if (idx < 36864){
      int pp    = idx & 1;
      int n8    = (idx >> 1) & 3;
      int lane2 = (idx >> 3) & 31;
      int warpN = (idx >> 8) & 1;
      int tap   = (idx >> 9) % 9;
      int rest  = (idx >> 9) / 9;
      int cgp   = rest & 3;
      int br    = rest >> 2;
      int qid2  = lane2 >> 2;
      int rid2  = lane2 & 3;
      int co = warpN*32 + n8*8 + qid2;
      int ci = cgp*16 + 2*rid2 + 8*pp;
      float w0 = conv_w[(co*128 + br*64 + ci)*9 + tap];
      float w1 = conv_w[(co*128 + br*64 + ci + 1)*9 + tap];
      __half2 h = __floats2half2_rn(w0, w1);
      int u2 = ((((br*4+cgp)*9 + tap)*2 + warpN)*32 + lane2)*4 + n8;
      g_wB2[u2*2 + pp] = *(uint32_t*)&h;
    }
    return;
  }

  extern __shared__ uint32_t S[];
  uint32_t* sA = S;
  uint32_t* sX = S + PW_AW;
  float* sScale = (float*)(S + PW_AW + PW_XW);
  float* sShift = sScale + 64;

  int sel = blockIdx.y;
  const float* x     = sel ? xv : xu;
  const float* w     = sel ? wv : wu;
  const float* gamma = sel ? gammav : gammau;
  const float* beta  = sel ? betav  : betau;
  const float* mean  = sel ? meanv  : meanu;
  const float* var   = sel ? varv   : varu;
  __half* out = sel ? g_vfh : g_ufh;

  int wid  = tid >> 5;
  int lane = tid & 31;
  int qid  = lane >> 2;
  int rid  = lane & 3;

  int img = blockIdx.x >> 6;
  int px0 = (blockIdx.x & 63) << 8;
  const float* xi = x + (size_t)img*IMGSZ + px0;

  for (int i = tid; i < 2048; i += 256){
    int co = i >> 5, pr = i & 31;
    float2 v = *(const float2*)(w + co*64 + pr*2);
    __half2 h = __floats2half2_rn(v.x, v.y);
    sA[co*PW_PA + pr] = *(uint32_t*)&h;
  }
  if (tid < 64){
    float la = gamma[tid]*rsqrtf(var[tid]+1e-5f);
    sScale[tid] = la;
    sShift[tid] = beta[tid] - mean[tid]*la;
  }
  #pragma unroll
  for (int pl = 0; pl < 4; ++pl){
    int p = wid*4 + pl;
    const float* pe = xi + (size_t)(2*p)*HW;
    const float* po = xi + (size_t)(2*p+1)*HW;
    uint32_t* d = sX + p*PW_PX;
    #pragma unroll
    for (int rep = 0; rep < 8; ++rep){
      int px = lane + rep*32;
      __half2 h = __floats2half2_rn(pe[px], po[px]);
      d[px] = *(uint32_t*)&h;
    }
  }
  __syncthreads();

  int pw0 = wid << 5;
  float acc[4][4][4];
  #pragma unroll
  for (int t=0;t<4;t++)
    #pragma unroll
    for (int n=0;n<4;n++)
      #pragma unroll
      for (int e=0;e<4;e++) acc[t][n][e]=0.f;

  #pragma unroll
  for (int ks = 0; ks < 4; ++ks){
    int c0p = ks*8;
    uint32_t bfr[4][2];
    #pragma unroll
    for (int n8 = 0; n8 < 4; ++n8){
      bfr[n8][0] = sX[(c0p+rid)*PW_PX   + pw0 + n8*8 + qid];
      bfr[n8][1] = sX[(c0p+4+rid)*PW_PX + pw0 + n8*8 + qid];
    }
    #pragma unroll
    for (int t = 0; t < 4; ++t){
      const uint32_t* ap = sA + (t*16 + qid)*PW_PA + c0p + rid;
      uint32_t afr[4];
      afr[0] = ap[0];
      afr[1] = ap[8*PW_PA];
      afr[2] = ap[4];
      afr[3] = ap[8*PW_PA + 4];
      #pragma unroll
      for (int n8 = 0; n8 < 4; ++n8)
        mma_f16(acc[t][n8], afr, bfr[n8]);
    }
  }

  __half* ob = out + (size_t)img*IMGSZ + px0 + pw0;
  #pragma unroll
  for (int t = 0; t < 4; ++t){
    int co0t = t*16 + qid;
    float la0 = sScale[co0t],   sa0 = sShift[co0t];
    float la1 = sScale[co0t+8], sa1 = sShift[co0t+8];
    #pragma unroll
    for (int n8 = 0; n8 < 4; ++n8){
      int pc = n8*8 + rid*2;
      __half2 h0 = __floats2half2_rn(
          fmaxf(fmaf(acc[t][n8][0], la0, sa0), 0.f),
          fmaxf(fmaf(acc[t][n8][1], la0, sa0), 0.f));
      __half2 h1 = __floats2half2_rn(
          fmaxf(fmaf(acc[t][n8][2], la1, sa1), 0.f),
          fmaxf(fmaf(acc[t][n8][3], la1, sa1), 0.f));
      *(uint32_t*)(ob + (size_t)co0t*HW + pc)     = *(uint32_t*)&h0;
      *(uint32_t*)(ob + (size_t)(co0t+8)*HW + pc) = *(uint32_t*)&h1;
    }
  }
}

// ---------------------------------------------------------------------------
// K2: 3x3 conv, mma.sync FP16 m16n8k16, v8 (= R11 v6 + quad B-frag LDG.128):
// - A tile packed as uint2 groups (.x = ci-pair P, .y = pair P+4) -> LDS.64
// - B frags: 2x LDG.128 per tap from g_wB2 (coalesced, L1-resident)
// - 27.1 KB smem -> 4 CTAs/SM; no mainloop barriers
// ---------------------------------------------------------------------------
#define GSTR 212                 // uint2 per group slice (6*35 + 2 pad)
#define AROWP 35                 // uint2 per row
#define CONV_SMEM (16*GSTR*8)    // 27136 B

__global__ void __launch_bounds__(256, 4) k_conv_mma()
{
  extern __shared__ uint2 sA2[];   // [group(16)][6r][35c]

  int tid  = threadIdx.x;
  int wid  = tid >> 5;
  int lane = tid & 31;
  int qid  = lane >> 2;
  int rid  = lane & 3;

  int bx  = blockIdx.x;
  int img = bx >> 7;
  int t   = bx & 127;
  int h0  = (t >> 2) << 2;
  int w0  = (t & 3)  << 5;
  int wset = img >> 3;
  const __half* in = (wset ? g_vfh : g_ufh) + (size_t)(img & 7)*IMGSZ;
  float* outp      = (wset ? g_ov  : g_ou ) + (size_t)(img & 7)*IMGSZ;

  // Stage: warp wid handles groups g = wid*2, wid*2+1.
  #pragma unroll
  for (int sub = 0; sub < 2; ++sub){
    int g  = wid*2 + sub;
    int P1 = ((g >> 2)*8) + (g & 3);
    const __half* p0 = in + (size_t)(2*P1)*HW;
    const __half* p1 = in + (size_t)(2*P1+1)*HW;
    const __half* p2 = in + (size_t)(2*P1+8)*HW;
    const __half* p3 = in + (size_t)(2*P1+9)*HW;
    uint2* dst = sA2 + g*GSTR;
    #pragma unroll
    for (int r = 0; r < 6; ++r){
      int gh = h0 + r - 1;
      bool vr = (unsigned)gh < 128u;
      int gw = w0 - 1 + lane;
      bool ok = vr && ((unsigned)gw < 128u);
      int off = gh*128 + gw;
      __half a = ok ? p0[off] : __half(0.f);
      __half b = ok ? p1[off] : __half(0.f);
      __half c = ok ? p2[off] : __half(0.f);
      __half d = ok ? p3[off] : __half(0.f);
      __half2 hx = __halves2half2(a, b);
      __half2 hy = __halves2half2(c, d);
      uint2 val; val.x = *(uint32_t*)&hx; val.y = *(uint32_t*)&hy;
      dst[r*AROWP + lane] = val;
      if (lane < 2){
        int gw2 = gw + 32;
        bool ok2 = vr && ((unsigned)gw2 < 128u);
        int off2 = gh*128 + gw2;
        __half a2 = ok2 ? p0[off2] : __half(0.f);
        __half b2 = ok2 ? p1[off2] : __half(0.f);
        __half c2 = ok2 ? p2[off2] : __half(0.f);
        __half d2 = ok2 ? p3[off2] : __half(0.f);
        __half2 hx2 = __halves2half2(a2, b2);
        __half2 hy2 = __halves2half2(c2, d2);
        uint2 v2; v2.x = *(uint32_t*)&hx2; v2.y = *(uint32_t*)&hy2;
        dst[r*AROWP + lane + 32] = v2;
      }
    }
  }
  __syncthreads();

  int warpM = wid & 3;
  int warpN = wid >> 2;
  int co0   = warpN << 5;

  float acc[2][4][4];
  #pragma unroll
  for (int a=0;a<2;a++)
    #pragma unroll
    for (int b=0;b<4;b++)
      #pragma unroll
      for (int e=0;e<4;e++) acc[a][b][e]=0.f;

  // uint4 base: ((((br*4+cgp)*9+tap)*2+warpN)*32+lane)*2
  const uint4* Bq0 = (const uint4*)g_wB2 + (size_t)wset*4608 + (warpN*32 + lane)*2;

  #pragma unroll
  for (int cgp = 0; cgp < 4; ++cgp){
    const uint2* Ab = sA2 + (cgp*4 + rid)*GSTR + warpM*AROWP + qid;
    const uint4* Bcg = Bq0 + cgp*1152;

    #pragma unroll
    for (int tap = 0; tap < 9; ++tap){
      int ky = tap / 3;
      int kx = tap - ky*3;
      int aoff = ky*AROWP + kx;

      uint4 b01 = __ldg(Bcg + tap*128);
      uint4 b23 = __ldg(Bcg + tap*128 + 1);
      uint32_t bfr[4][2];
      bfr[0][0] = b01.x; bfr[0][1] = b01.y;
      bfr[1][0] = b01.z; bfr[1][1] = b01.w;
      bfr[2][0] = b23.x; bfr[2][1] = b23.y;
      bfr[3][0] = b23.z; bfr[3][1] = b23.w;

      #pragma unroll
      for (int tt = 0; tt < 2; ++tt){
        uint2 v1 = Ab[aoff + tt*16];
        uint2 v2 = Ab[aoff + tt*16 + 8];
        uint32_t afr[4];
        afr[0] = v1.x;
        afr[1] = v2.x;
        afr[2] = v1.y;
        afr[3] = v2.y;
        #pragma unroll
        for (int n8 = 0; n8 < 4; ++n8)
          mma_f16(acc[tt][n8], afr, bfr[n8]);
      }
    }
  }

  // epilogue (same C mapping as R11)
  int h = h0 + warpM;
  float* ob = outp + h*128 + w0;
  #pragma unroll
  for (int tt = 0; tt < 2; ++tt){
    int wbase = tt*16 + qid;
    #pragma unroll
    for (int n8 = 0; n8 < 4; ++n8){
      int co = co0 + n8*8 + rid*2;
      ob[(size_t)co*HW + wbase]          = acc[tt][n8][0];
      ob[(size_t)(co+1)*HW + wbase]      = acc[tt][n8][1];
      ob[(size_t)co*HW + wbase + 8]      = acc[tt][n8][2];
      ob[(size_t)(co+1)*HW + wbase + 8]  = acc[tt][n8][3];
    }
  }
}

// ---------------------------------------------------------------------------
// K3: broadcast add, register-resident (R11 version — at BW floor).
// ---------------------------------------------------------------------------
__global__ void __launch_bounds__(256) k_bcast3(
    const float* __restrict__ bias, float* __restrict__ out)
{
  int tid = threadIdx.x;
  int blk = blockIdx.x & 15;
  int co  = (blockIdx.x >> 4) & 63;
  int b   = blockIdx.x >> 10;
  int px  = blk*1024 + tid*4;

  float bi = __ldg(bias + co);
  float4 uu[4], vv[4];
  #pragma unroll
  for (int s = 0; s < 4; ++s){
    uu[s] = __ldg((const float4*)(g_ou + (((size_t)((b*4+s)*64 + co))<<14) + px));
    vv[s] = __ldg((const float4*)(g_ov + (((size_t)((b*4+s)*64 + co))<<14) + px));
    uu[s].x += bi; uu[s].y += bi; uu[s].z += bi; uu[s].w += bi;
  }
  #pragma unroll
  for (int sx = 0; sx < 4; ++sx){
    #pragma unroll
    for (int sy = 0; sy < 4; ++sy){
      float4 o;
      o.x = uu[sx].x + vv[sy].x;
      o.y = uu[sx].y + vv[sy].y;
      o.z = uu[sx].z + vv[sy].z;
      o.w = uu[sx].w + vv[sy].w;
      __stcs((float4*)(out + (((size_t)((((b*4+sx)*4+sy)*64)+co))<<14) + px), o);
    }
  }
}

// ---------------------------------------------------------------------------
extern "C" void kernel_launch(void* const* d_in, const int* in_sizes, int n_in,
                              void* d_out, int out_size)
{
  const float* u        = (const float*)d_in[0];
  const float* v        = (const float*)d_in[1];
  const float* pu_w     = (const float*)d_in[2];
  const float* pu_gamma = (const float*)d_in[3];
  const float* pu_beta  = (const float*)d_in[4];
  const float* pu_mean  = (const float*)d_in[5];
  const float* pu_var   = (const float*)d_in[6];
  const float* pv_w     = (const float*)d_in[7];
  const float* pv_gamma = (const float*)d_in[8];
  const float* pv_beta  = (const float*)d_in[9];
  const float* pv_mean  = (const float*)d_in[10];
  const float* pv_var   = (const float*)d_in[11];
  const float* conv_w   = (const float*)d_in[12];
  const float* conv_b   = (const float*)d_in[13];
  float* out = (float*)d_out;

  static int attr_set = 0;
  if (!attr_set){
    cudaFuncSetAttribute(k_pw_mma,   cudaFuncAttributeMaxDynamicSharedMemorySize, PW_SMEM);
    cudaFuncSetAttribute(k_conv_mma, cudaFuncAttributeMaxDynamicSharedMemorySize, CONV_SMEM);
    attr_set = 1;
  }

  // grid (512, 3): y=0 u-branch pw, y=1 v-branch pw, y=2 conv-weight repack
  dim3 pwg(512, 3);
  k_pw_mma<<<pwg, 256, PW_SMEM>>>(u, v, pu_w, pv_w, pu_gamma, pv_gamma,
                                  pu_beta, pv_beta, pu_mean, pv_mean,
                                  pu_var, pv_var, conv_w);

  k_conv_mma<<<2048, 256, CONV_SMEM>>>();

  k_bcast3<<<2048, 256>>>(conv_b, out);
}

// round 14
// speedup vs baseline: 1.3925x; 1.1340x over previous
#include <cuda_runtime.h>
#include <cuda_fp16.h>
#include <cstdint>

#define NIMG 8
#define HW 16384           // 128*128
#define IMGSZ (64*HW)

// Scratch (device globals)
__device__ __half g_ufh[NIMG*IMGSZ];   // fp16 activations, plane layout [img][ci][px]
__device__ __half g_vfh[NIMG*IMGSZ];
__device__ float  g_ou[NIMG*IMGSZ];
__device__ float  g_ov[NIMG*IMGSZ];
// conv weights, k16 B-frag layout (R11-proven):
// [br(2)][cgp(4)][tap(9)][co(64)][rid(4)][pp(2)] of half2
__device__ uint32_t g_wPh[2*4*9*64*4*2];
// pw weights, k16 A-frag layout:
// uint2 idx = ((((br*4+cgp)*2+warpN)*2+tt)*2+rh)*32 + lane
// .x = half2 W[co][ci0+2rid .. +1], .y = half2 W[co][ci0+8+2rid .. +1]
// co = warpN*32 + tt*16 + rh*8 + qid, ci0 = cgp*16
__device__ uint2 g_wPw[2048];

// fp16 k16 mma: A 4 regs, B 2 regs, C 4 f32
__device__ __forceinline__ void mma_f16(float* c, const uint32_t* a, const uint32_t* b){
  asm volatile(
    "mma.sync.aligned.m16n8k16.row.col.f32.f16.f16.f32 "
    "{%0,%1,%2,%3}, {%4,%5,%6,%7}, {%8,%9}, {%0,%1,%2,%3};"
    : "+f"(c[0]), "+f"(c[1]), "+f"(c[2]), "+f"(c[3])
    : "r"(a[0]), "r"(a[1]), "r"(a[2]), "r"(a[3]), "r"(b[0]), "r"(b[1]));
}

// ---------------------------------------------------------------------------
// K0: pack conv weights (R11 layout) + pw weights (A-frag layout)
// ---------------------------------------------------------------------------
__global__ void k_prep_w(const float* __restrict__ conv_w,
                         const float* __restrict__ pu_w,
                         const float* __restrict__ pv_w){
  int idx = blockIdx.x*256 + threadIdx.x;
  if (idx < 36864){
    int pp  = idx & 1;
    int rid = (idx >> 1) & 3;
    int co  = (idx >> 3) & 63;
    int tap = (idx >> 9) % 9;
    int rest= (idx >> 9) / 9;
    int cgp = rest & 3;
    int br  = rest >> 2;
    int ci  = cgp*16 + 2*rid + 8*pp;
    float w0 = conv_w[(co*128 + br*64 + ci)*9 + tap];
    float w1 = conv_w[(co*128 + br*64 + ci + 1)*9 + tap];
    __half2 h = __floats2half2_rn(w0, w1);
    g_wPh[idx] = *(uint32_t*)&h;
    return;
  }
  int j = idx - 36864;
  if (j >= 2048) return;
  int lane = j & 31;
  int rh   = (j >> 5) & 1;
  int tt   = (j >> 6) & 1;
  int wN   = (j >> 7) & 1;
  int cgp  = (j >> 8) & 3;
  int br   = (j >> 10) & 1;
  int qid  = lane >> 2;
  int rid  = lane & 3;
  int co   = wN*32 + tt*16 + rh*8 + qid;
  int ci0  = cgp*16;
  const float* w = br ? pv_w : pu_w;
  __half2 hx = __floats2half2_rn(w[co*64 + ci0 + 2*rid],     w[co*64 + ci0 + 2*rid + 1]);
  __half2 hy = __floats2half2_rn(w[co*64 + ci0 + 8 + 2*rid], w[co*64 + ci0 + 8 + 2*rid + 1]);
  uint2 val; val.x = *(uint32_t*)&hx; val.y = *(uint32_t*)&hy;
  g_wPw[j] = val;
}

// ---------------------------------------------------------------------------
// K1: 1x1 conv + BN + ReLU, v3 (occupancy build):
// CTA = 128 px, one image, one branch (grid 2048). Warp = 32 co x 32 px.
// acc = 32 regs; weights via __ldg (4KB L1-resident); acts staged once in
// conv-proven uint2-group layout. 17KB smem -> 4 CTAs/SM.
// ---------------------------------------------------------------------------
#define PWG 132                       // uint2 pitch per group (264 words %32==8)
#define PW_SMEM (16*PWG*8 + 512)      // 17408 B

__global__ void __launch_bounds__(256, 4) k_pw_mma(
    const float* __restrict__ xu, const float* __restrict__ xv,
    const float* __restrict__ gammau, const float* __restrict__ gammav,
    const float* __restrict__ betau,  const float* __restrict__ betav,
    const float* __restrict__ meanu,  const float* __restrict__ meanv,
    const float* __restrict__ varu,   const float* __restrict__ varv)
{
  extern __shared__ uint2 sX2[];      // [group(16)][PWG]
  float* sScale = (float*)(sX2 + 16*PWG);
  float* sShift = sScale + 64;

  int tid  = threadIdx.x;
  int wid  = tid >> 5;
  int lane = tid & 31;
  int qid  = lane >> 2;
  int rid  = lane & 3;

  int bx  = blockIdx.x;
  int sel = bx >> 10;
  int img = (bx >> 7) & 7;
  int px0 = (bx & 127) << 7;
  const float* x     = sel ? xv : xu;
  const float* gamma = sel ? gammav : gammau;
  const float* beta  = sel ? betav  : betau;
  const float* mean  = sel ? meanv  : meanu;
  const float* var   = sel ? varv   : varu;
  __half* out = sel ? g_vfh : g_ufh;

  const float* xi = x + (size_t)img*IMGSZ + px0;

  if (tid < 64){
    float la = gamma[tid]*rsqrtf(var[tid]+1e-5f);
    sScale[tid] = la;
    sShift[tid] = beta[tid] - mean[tid]*la;
  }

  // stage activations: warp wid handles groups g = wid*2, wid*2+1
  #pragma unroll
  for (int sub = 0; sub < 2; ++sub){
    int g  = wid*2 + sub;
    int P1 = ((g >> 2)*8) + (g & 3);
    const float* p0 = xi + (size_t)(2*P1)*HW;
    const float* p1 = xi + (size_t)(2*P1+1)*HW;
    const float* p2 = xi + (size_t)(2*P1+8)*HW;
    const float* p3 = xi + (size_t)(2*P1+9)*HW;
    uint2* dst = sX2 + g*PWG;
    #pragma unroll
    for (int rep = 0; rep < 4; ++rep){
      int px = lane + rep*32;
      __half2 hx = __floats2half2_rn(p0[px], p1[px]);
      __half2 hy = __floats2half2_rn(p2[px], p3[px]);
      uint2 val; val.x = *(uint32_t*)&hx; val.y = *(uint32_t*)&hy;
      dst[px] = val;
    }
  }
  __syncthreads();

  int warpM = wid & 3;          // px sub-tile
  int warpN = wid >> 2;         // co half
  int pxw0  = warpM << 5;
  int co0   = warpN << 5;

  float acc[2][4][4];
  #pragma unroll
  for (int a=0;a<2;a++)
    #pragma unroll
    for (int b=0;b<4;b++)
      #pragma unroll
      for (int e=0;e<4;e++) acc[a][b][e]=0.f;

  #pragma unroll
  for (int cgp = 0; cgp < 4; ++cgp){
    // A frags (weights) via __ldg
    uint32_t afr[2][4];
    #pragma unroll
    for (int tt = 0; tt < 2; ++tt){
      int base = ((((sel*4+cgp)*2 + warpN)*2 + tt)*2)*32 + lane;
      uint2 w0 = __ldg(g_wPw + base);         // rh = 0
      uint2 w1 = __ldg(g_wPw + base + 32);    // rh = 1
      afr[tt][0] = w0.x;
      afr[tt][1] = w1.x;
      afr[tt][2] = w0.y;
      afr[tt][3] = w1.y;
    }
    const uint2* Ab = sX2 + (cgp*4 + rid)*PWG + pxw0 + qid;
    #pragma unroll
    for (int n8 = 0; n8 < 4; ++n8){
      uint2 bv = Ab[n8*8];
      uint32_t bfr[2];
      bfr[0] = bv.x;
      bfr[1] = bv.y;
      #pragma unroll
      for (int tt = 0; tt < 2; ++tt)
        mma_f16(acc[tt][n8], afr[tt], bfr);
    }
  }

  // epilogue: BN + ReLU -> fp16 plane layout
  __half* ob = out + (size_t)img*IMGSZ + px0 + pxw0;
  #pragma unroll
  for (int tt = 0; tt < 2; ++tt){
    int ct  = co0 + tt*16;
    float la0 = sScale[ct+qid],   sa0 = sShift[ct+qid];
    float la1 = sScale[ct+qid+8], sa1 = sShift[ct+qid+8];
    #pragma unroll
    for (int n8 = 0; n8 < 4; ++n8){
      int pc = n8*8 + rid*2;
      __half2 h0 = __floats2half2_rn(
          fmaxf(fmaf(acc[tt][n8][0], la0, sa0), 0.f),
          fmaxf(fmaf(acc[tt][n8][1], la0, sa0), 0.f));
      __half2 h1 = __floats2half2_rn(
          fmaxf(fmaf(acc[tt][n8][2], la1, sa1), 0.f),
          fmaxf(fmaf(acc[tt][n8][3], la1, sa1), 0.f));
      *(uint32_t*)(ob + (size_t)(ct+qid)*HW + pc)   = *(uint32_t*)&h0;
      *(uint32_t*)(ob + (size_t)(ct+qid+8)*HW + pc) = *(uint32_t*)&h1;
    }
  }
}

// ---------------------------------------------------------------------------
// K2: 3x3 conv, mma.sync FP16 m16n8k16 — EXACT R11 v6 (best measured).
// ---------------------------------------------------------------------------
#define GSTR 212                 // uint2 per group slice (6*35 + 2 pad)
#define AROWP 35                 // uint2 per row
#define CONV_SMEM (16*GSTR*8)    // 27136 B

__global__ void __launch_bounds__(256, 4) k_conv_mma()
{
  extern __shared__ uint2 sA2[];   // [group(16)][6r][35c]

  int tid  = threadIdx.x;
  int wid  = tid >> 5;
  int lane = tid & 31;
  int qid  = lane >> 2;
  int rid  = lane & 3;

  int bx  = blockIdx.x;
  int img = bx >> 7;
  int t   = bx & 127;
  int h0  = (t >> 2) << 2;
  int w0  = (t & 3)  << 5;
  int wset = img >> 3;
  const __half* in = (wset ? g_vfh : g_ufh) + (size_t)(img & 7)*IMGSZ;
  float* outp      = (wset ? g_ov  : g_ou ) + (size_t)(img & 7)*IMGSZ;

  #pragma unroll
  for (int sub = 0; sub < 2; ++sub){
    int g  = wid*2 + sub;
    int P1 = ((g >> 2)*8) + (g & 3);
    const __half* p0 = in + (size_t)(2*P1)*HW;
    const __half* p1 = in + (size_t)(2*P1+1)*HW;
    const __half* p2 = in + (size_t)(2*P1+8)*HW;
    const __half* p3 = in + (size_t)(2*P1+9)*HW;
    uint2* dst = sA2 + g*GSTR;
    #pragma unroll
    for (int r = 0; r < 6; ++r){
      int gh = h0 + r - 1;
      bool vr = (unsigned)gh < 128u;
      int gw = w0 - 1 + lane;
      bool ok = vr && ((unsigned)gw < 128u);
      int off = gh*128 + gw;
      __half a = ok ? p0[off] : __half(0.f);
      __half b = ok ? p1[off] : __half(0.f);
      __half c = ok ? p2[off] : __half(0.f);
      __half d = ok ? p3[off] : __half(0.f);
      __half2 hx = __halves2half2(a, b);
      __half2 hy = __halves2half2(c, d);
      uint2 val; val.x = *(uint32_t*)&hx; val.y = *(uint32_t*)&hy;
      dst[r*AROWP + lane] = val;
      if (lane < 2){
        int gw2 = gw + 32;
        bool ok2 = vr && ((unsigned)gw2 < 128u);
        int off2 = gh*128 + gw2;
        __half a2 = ok2 ? p0[off2] : __half(0.f);
        __half b2 = ok2 ? p1[off2] : __half(0.f);
        __half c2 = ok2 ? p2[off2] : __half(0.f);
        __half d2 = ok2 ? p3[off2] : __half(0.f);
        __half2 hx2 = __halves2half2(a2, b2);
        __half2 hy2 = __halves2half2(c2, d2);
        uint2 v2; v2.x = *(uint32_t*)&hx2; v2.y = *(uint32_t*)&hy2;
        dst[r*AROWP + lane + 32] = v2;
      }
    }
  }
  __syncthreads();

  int warpM = wid & 3;
  int co0   = (wid >> 2) << 5;

  float acc[2][4][4];
  #pragma unroll
  for (int a=0;a<2;a++)
    #pragma unroll
    for (int b=0;b<4;b++)
      #pragma unroll
      for (int e=0;e<4;e++) acc[a][b][e]=0.f;

  const uint2* Bb0 = (const uint2*)(g_wPh + (size_t)wset*18432) + (co0 + qid)*4 + rid;

  #pragma unroll
  for (int cgp = 0; cgp < 4; ++cgp){
    const uint2* Ab = sA2 + (cgp*4 + rid)*GSTR + warpM*AROWP + qid;
    const uint2* Bb = Bb0 + cgp*2304;

    #pragma unroll
    for (int tap = 0; tap < 9; ++tap){
      int ky = tap / 3;
      int kx = tap - ky*3;
      int aoff = ky*AROWP + kx;

      uint32_t bfr[4][2];
      #pragma unroll
      for (int n8 = 0; n8 < 4; ++n8){
        uint2 bp = __ldg(Bb + tap*256 + n8*32);
        bfr[n8][0] = bp.x;
        bfr[n8][1] = bp.y;
      }
      #pragma unroll
      for (int tt = 0; tt < 2; ++tt){
        uint2 v1 = Ab[aoff + tt*16];
        uint2 v2 = Ab[aoff + tt*16 + 8];
        uint32_t afr[4];
        afr[0] = v1.x;
        afr[1] = v2.x;
        afr[2] = v1.y;
        afr[3] = v2.y;
        #pragma unroll
        for (int n8 = 0; n8 < 4; ++n8)
          mma_f16(acc[tt][n8], afr, bfr[n8]);
      }
    }
  }

  int h = h0 + warpM;
  float* ob = outp + h*128 + w0;
  #pragma unroll
  for (int tt = 0; tt < 2; ++tt){
    int wbase = tt*16 + qid;
    #pragma unroll
    for (int n8 = 0; n8 < 4; ++n8){
      int co = co0 + n8*8 + rid*2;
      ob[(size_t)co*HW + wbase]          = acc[tt][n8][0];
      ob[(size_t)(co+1)*HW + wbase]      = acc[tt][n8][1];
      ob[(size_t)co*HW + wbase + 8]      = acc[tt][n8][2];
      ob[(size_t)(co+1)*HW + wbase + 8]  = acc[tt][n8][3];
    }
  }
}

// ---------------------------------------------------------------------------
// K3: broadcast add, register-resident (R11 version — at BW floor).
// ---------------------------------------------------------------------------
__global__ void __launch_bounds__(256) k_bcast3(
    const float* __restrict__ bias, float* __restrict__ out)
{
  int tid = threadIdx.x;
  int blk = blockIdx.x & 15;
  int co  = (blockIdx.x >> 4) & 63;
  int b   = blockIdx.x >> 10;
  int px  = blk*1024 + tid*4;

  float bi = __ldg(bias + co);
  float4 uu[4], vv[4];
  #pragma unroll
  for (int s = 0; s < 4; ++s){
    uu[s] = __ldg((const float4*)(g_ou + (((size_t)((b*4+s)*64 + co))<<14) + px));
    vv[s] = __ldg((const float4*)(g_ov + (((size_t)((b*4+s)*64 + co))<<14) + px));
    uu[s].x += bi; uu[s].y += bi; uu[s].z += bi; uu[s].w += bi;
  }
  #pragma unroll
  for (int sx = 0; sx < 4; ++sx){
    #pragma unroll
    for (int sy = 0; sy < 4; ++sy){
      float4 o;
      o.x = uu[sx].x + vv[sy].x;
      o.y = uu[sx].y + vv[sy].y;
      o.z = uu[sx].z + vv[sy].z;
      o.w = uu[sx].w + vv[sy].w;
      __stcs((float4*)(out + (((size_t)((((b*4+sx)*4+sy)*64)+co))<<14) + px), o);
    }
  }
}

// ---------------------------------------------------------------------------
extern "C" void kernel_launch(void* const* d_in, const int* in_sizes, int n_in,
                              void* d_out, int out_size)
{
  const float* u        = (const float*)d_in[0];
  const float* v        = (const float*)d_in[1];
  const float* pu_w     = (const float*)d_in[2];
  const float* pu_gamma = (const float*)d_in[3];
  const float* pu_beta  = (const float*)d_in[4];
  const float* pu_mean  = (const float*)d_in[5];
  const float* pu_var   = (const float*)d_in[6];
  const float* pv_w     = (const float*)d_in[7];
  const float* pv_gamma = (const float*)d_in[8];
  const float* pv_beta  = (const float*)d_in[9];
  const float* pv_mean  = (const float*)d_in[10];
  const float* pv_var   = (const float*)d_in[11];
  const float* conv_w   = (const float*)d_in[12];
  const float* conv_b   = (const float*)d_in[13];
  float* out = (float*)d_out;

  static int attr_set = 0;
  if (!attr_set){
    cudaFuncSetAttribute(k_pw_mma,   cudaFuncAttributeMaxDynamicSharedMemorySize, PW_SMEM);
    cudaFuncSetAttribute(k_conv_mma, cudaFuncAttributeMaxDynamicSharedMemorySize, CONV_SMEM);
    attr_set = 1;
  }

  k_prep_w<<<152, 256>>>(conv_w, pu_w, pv_w);

  k_pw_mma<<<2048, 256, PW_SMEM>>>(u, v, pu_gamma, pv_gamma,
                                   pu_beta, pv_beta, pu_mean, pv_mean,
                                   pu_var, pv_var);

  k_conv_mma<<<2048, 256, CONV_SMEM>>>();

  k_bcast3<<<2048, 256>>>(conv_b, out);
}